// round 2
// baseline (speedup 1.0000x reference)
#include <cuda_runtime.h>
#include <math.h>

#define D       256
#define TM      64
#define NTHR    512
#define KC      16
#define EPS     1e-5f

typedef unsigned long long u64;

// ---- packed fp32x2 helpers (sm_103a FFMA2 path, only reachable via PTX) ----
__device__ __forceinline__ u64 ffma2(u64 a, u64 b, u64 c) {
    u64 d;
    asm("fma.rn.f32x2 %0, %1, %2, %3;" : "=l"(d) : "l"(a), "l"(b), "l"(c));
    return d;
}
__device__ __forceinline__ u64 packdup(float x) {
    u64 r;
    asm("mov.b64 %0, {%1, %1};" : "=l"(r) : "f"(x));
    return r;
}
__device__ __forceinline__ float2 unpack2(u64 v) {
    float2 f;
    asm("mov.b64 {%0, %1}, %2;" : "=f"(f.x), "=f"(f.y) : "l"(v));
    return f;
}

__device__ __forceinline__ float gelu_exact(float x) {
    return 0.5f * x * (1.0f + erff(x * 0.70710678118654752f));
}

// ---- fused GEMM tile: acc[4][4](f32x2) = As(64xD, smem) @ Wg(DxD, gmem) ----
// Thread (tid): rows trow..trow+3 (trow=(tid>>5)*4), col pairs tcol+64j (tcol=(tid&31)*2)
__device__ __forceinline__ void gemm_tile(const float* __restrict__ As,
                                          const float* __restrict__ Wg,
                                          float* ws, u64 acc[4][4], int tid) {
    const int trow = (tid >> 5) * 4;
    const int tcol = (tid & 31) * 2;
#pragma unroll
    for (int r = 0; r < 4; r++)
#pragma unroll
        for (int j = 0; j < 4; j++) acc[r][j] = 0ULL;

    for (int k0 = 0; k0 < D; k0 += KC) {
        // cooperative load of W chunk rows [k0, k0+KC) -> ws (contiguous, coalesced)
        const float4* src = (const float4*)(Wg + k0 * D);
        float4* dst = (float4*)ws;
        dst[tid]        = src[tid];
        dst[tid + NTHR] = src[tid + NTHR];
        __syncthreads();
#pragma unroll
        for (int kk = 0; kk < KC; kk += 4) {
            float4 a4[4];
#pragma unroll
            for (int r = 0; r < 4; r++)
                a4[r] = *(const float4*)(As + (trow + r) * D + k0 + kk);
#pragma unroll
            for (int u = 0; u < 4; u++) {
                u64 av[4];
#pragma unroll
                for (int r = 0; r < 4; r++)
                    av[r] = packdup(((const float*)&a4[r])[u]);
#pragma unroll
                for (int j = 0; j < 4; j++) {
                    u64 b2 = *(const u64*)(ws + (kk + u) * D + tcol + 64 * j);
#pragma unroll
                    for (int r = 0; r < 4; r++)
                        acc[r][j] = ffma2(av[r], b2, acc[r][j]);
                }
            }
        }
        __syncthreads();
    }
}

// ---- per-row layernorm of a 64xD smem tile ----
__device__ __forceinline__ void layernorm_tile(const float* __restrict__ xs,
                                               float* __restrict__ hs,
                                               const float* __restrict__ g,
                                               const float* __restrict__ be, int tid) {
    const int warp = tid >> 5, lane = tid & 31;
#pragma unroll
    for (int rr = 0; rr < 4; rr++) {
        const int r = warp * 4 + rr;
        const float* row = xs + r * D;
        float s = 0.f, s2 = 0.f;
#pragma unroll
        for (int c = lane; c < D; c += 32) { float v = row[c]; s += v; s2 += v * v; }
#pragma unroll
        for (int o = 16; o; o >>= 1) {
            s  += __shfl_xor_sync(0xFFFFFFFFu, s,  o);
            s2 += __shfl_xor_sync(0xFFFFFFFFu, s2, o);
        }
        const float mu   = s * (1.0f / D);
        const float var  = s2 * (1.0f / D) - mu * mu;
        const float rstd = rsqrtf(var + EPS);
#pragma unroll
        for (int c = lane; c < D; c += 32)
            hs[r * D + c] = (row[c] - mu) * rstd * g[c] + be[c];
    }
}

__global__ __launch_bounds__(NTHR, 1)
void stab_embed_fused(const float* __restrict__ meas, const float* __restrict__ event,
                      const float* __restrict__ leak, const float* __restrict__ event_leak,
                      const int* __restrict__ stab_ids, const int* __restrict__ cycle_ids,
                      const float* __restrict__ w_meas, const float* __restrict__ b_meas,
                      const float* __restrict__ w_event, const float* __restrict__ b_event,
                      const float* __restrict__ w_leak, const float* __restrict__ b_leak,
                      const float* __restrict__ w_el, const float* __restrict__ b_el,
                      const float* __restrict__ stab_table, const float* __restrict__ cycle_table,
                      const float* __restrict__ g1, const float* __restrict__ be1,
                      const float* __restrict__ W11, const float* __restrict__ b11,
                      const float* __restrict__ W12, const float* __restrict__ b12,
                      const float* __restrict__ g2, const float* __restrict__ be2,
                      const float* __restrict__ W21, const float* __restrict__ b21,
                      const float* __restrict__ W22, const float* __restrict__ b22,
                      float* __restrict__ out) {
    extern __shared__ float smem[];
    float* xs = smem;              // 64 x 256  residual stream
    float* hs = smem + TM * D;     // 64 x 256  LN / GELU activations
    float* ws = smem + 2 * TM * D; // KC x 256  streamed weight chunk

    const int tid  = threadIdx.x;
    const int base = blockIdx.x * TM;

    // ---- embed: 4 scalar projections + 2 table gathers -> xs ----
    {
        const int r  = tid >> 3;            // 64 rows
        const int c0 = (tid & 7) * 32;      // 32 cols each
        const int gr = base + r;
        const float m  = meas[gr], e = event[gr], l = leak[gr], el = event_leak[gr];
        const float* srow = stab_table  + (size_t)stab_ids[gr]  * D;
        const float* crow = cycle_table + (size_t)cycle_ids[gr] * D;
#pragma unroll
        for (int c = c0; c < c0 + 32; c++) {
            xs[r * D + c] = m * w_meas[c] + b_meas[c]
                          + e * w_event[c] + b_event[c]
                          + l * w_leak[c] + b_leak[c]
                          + el * w_el[c] + b_el[c]
                          + srow[c] + crow[c];
        }
    }
    __syncthreads();

    const int trow = (tid >> 5) * 4;
    const int tcol = (tid & 31) * 2;
    u64 acc[4][4];

    // ================= residual block 1 =================
    layernorm_tile(xs, hs, g1, be1, tid);
    __syncthreads();

    gemm_tile(hs, W11, ws, acc, tid);           // trailing sync inside covers hs reads
#pragma unroll
    for (int r = 0; r < 4; r++)
#pragma unroll
        for (int j = 0; j < 4; j++) {
            const int col = tcol + 64 * j;
            float2 v = unpack2(acc[r][j]);
            hs[(trow + r) * D + col]     = gelu_exact(v.x + b11[col]);
            hs[(trow + r) * D + col + 1] = gelu_exact(v.y + b11[col + 1]);
        }
    __syncthreads();

    gemm_tile(hs, W12, ws, acc, tid);
#pragma unroll
    for (int r = 0; r < 4; r++)
#pragma unroll
        for (int j = 0; j < 4; j++) {
            const int col = tcol + 64 * j;
            float2 v = unpack2(acc[r][j]);
            xs[(trow + r) * D + col]     += v.x + b12[col];
            xs[(trow + r) * D + col + 1] += v.y + b12[col + 1];
        }
    __syncthreads();

    // ================= residual block 2 =================
    layernorm_tile(xs, hs, g2, be2, tid);
    __syncthreads();

    gemm_tile(hs, W21, ws, acc, tid);
#pragma unroll
    for (int r = 0; r < 4; r++)
#pragma unroll
        for (int j = 0; j < 4; j++) {
            const int col = tcol + 64 * j;
            float2 v = unpack2(acc[r][j]);
            hs[(trow + r) * D + col]     = gelu_exact(v.x + b21[col]);
            hs[(trow + r) * D + col + 1] = gelu_exact(v.y + b21[col + 1]);
        }
    __syncthreads();

    gemm_tile(hs, W22, ws, acc, tid);
#pragma unroll
    for (int r = 0; r < 4; r++)
#pragma unroll
        for (int j = 0; j < 4; j++) {
            const int col = tcol + 64 * j;
            float2 v = unpack2(acc[r][j]);
            const size_t o = (size_t)(base + trow + r) * D + col;
            out[o]     = xs[(trow + r) * D + col]     + v.x + b22[col];
            out[o + 1] = xs[(trow + r) * D + col + 1] + v.y + b22[col + 1];
        }
}

extern "C" void kernel_launch(void* const* d_in, const int* in_sizes, int n_in,
                              void* d_out, int out_size) {
    const float* meas       = (const float*)d_in[0];
    const float* event      = (const float*)d_in[1];
    const float* leak       = (const float*)d_in[2];
    const float* event_leak = (const float*)d_in[3];
    const int*   stab_ids   = (const int*)d_in[4];
    const int*   cycle_ids  = (const int*)d_in[5];
    const float* w_meas  = (const float*)d_in[6];
    const float* b_meas  = (const float*)d_in[7];
    const float* w_event = (const float*)d_in[8];
    const float* b_event = (const float*)d_in[9];
    const float* w_leak  = (const float*)d_in[10];
    const float* b_leak  = (const float*)d_in[11];
    const float* w_el    = (const float*)d_in[12];
    const float* b_el    = (const float*)d_in[13];
    const float* stab_table  = (const float*)d_in[14];
    const float* cycle_table = (const float*)d_in[15];
    const float* g1  = (const float*)d_in[16];
    const float* be1 = (const float*)d_in[17];
    const float* W11 = (const float*)d_in[18];
    const float* b11 = (const float*)d_in[19];
    const float* W12 = (const float*)d_in[20];
    const float* b12 = (const float*)d_in[21];
    const float* g2  = (const float*)d_in[22];
    const float* be2 = (const float*)d_in[23];
    const float* W21 = (const float*)d_in[24];
    const float* b21 = (const float*)d_in[25];
    const float* W22 = (const float*)d_in[26];
    const float* b22 = (const float*)d_in[27];

    const int n_tokens = in_sizes[0];          // B*S = 262144
    const int nblocks  = n_tokens / TM;        // 4096
    const int smem_bytes = (2 * TM * D + KC * D) * (int)sizeof(float);  // 147456

    cudaFuncSetAttribute(stab_embed_fused,
                         cudaFuncAttributeMaxDynamicSharedMemorySize, smem_bytes);

    stab_embed_fused<<<nblocks, NTHR, smem_bytes>>>(
        meas, event, leak, event_leak, stab_ids, cycle_ids,
        w_meas, b_meas, w_event, b_event, w_leak, b_leak, w_el, b_el,
        stab_table, cycle_table,
        g1, be1, W11, b11, W12, b12,
        g2, be2, W21, b21, W22, b22,
        (float*)d_out);
}

// round 3
// speedup vs baseline: 1.0005x; 1.0005x over previous
#include <cuda_runtime.h>
#include <math.h>

#define D       256
#define TM      64
#define NTHR    512
#define KC      16
#define EPS     1e-5f

typedef unsigned long long u64;

// ---- packed fp32x2 helpers (sm_103a FFMA2 path, only reachable via PTX) ----
__device__ __forceinline__ u64 ffma2(u64 a, u64 b, u64 c) {
    u64 d;
    asm("fma.rn.f32x2 %0, %1, %2, %3;" : "=l"(d) : "l"(a), "l"(b), "l"(c));
    return d;
}
__device__ __forceinline__ u64 packdup(float x) {
    u64 r;
    asm("mov.b64 %0, {%1, %1};" : "=l"(r) : "f"(x));
    return r;
}
__device__ __forceinline__ float2 unpack2(u64 v) {
    float2 f;
    asm("mov.b64 {%0, %1}, %2;" : "=f"(f.x), "=f"(f.y) : "l"(v));
    return f;
}

__device__ __forceinline__ float gelu_exact(float x) {
    return 0.5f * x * (1.0f + erff(x * 0.70710678118654752f));
}

// ---- fused GEMM tile: acc[4][4](f32x2) = As(64xD, smem) @ Wg(DxD, gmem) ----
// Thread (tid): rows trow..trow+3 (trow=(tid>>5)*4), col pairs tcol+64j (tcol=(tid&31)*2)
__device__ __forceinline__ void gemm_tile(const float* __restrict__ As,
                                          const float* __restrict__ Wg,
                                          float* ws, u64 acc[4][4], int tid) {
    const int trow = (tid >> 5) * 4;
    const int tcol = (tid & 31) * 2;
#pragma unroll
    for (int r = 0; r < 4; r++)
#pragma unroll
        for (int j = 0; j < 4; j++) acc[r][j] = 0ULL;

    for (int k0 = 0; k0 < D; k0 += KC) {
        // cooperative load of W chunk rows [k0, k0+KC) -> ws (contiguous, coalesced)
        const float4* src = (const float4*)(Wg + k0 * D);
        float4* dst = (float4*)ws;
        dst[tid]        = src[tid];
        dst[tid + NTHR] = src[tid + NTHR];
        __syncthreads();
#pragma unroll
        for (int kk = 0; kk < KC; kk += 4) {
            float4 a4[4];
#pragma unroll
            for (int r = 0; r < 4; r++)
                a4[r] = *(const float4*)(As + (trow + r) * D + k0 + kk);
#pragma unroll
            for (int u = 0; u < 4; u++) {
                u64 av[4];
#pragma unroll
                for (int r = 0; r < 4; r++)
                    av[r] = packdup(((const float*)&a4[r])[u]);
#pragma unroll
                for (int j = 0; j < 4; j++) {
                    u64 b2 = *(const u64*)(ws + (kk + u) * D + tcol + 64 * j);
#pragma unroll
                    for (int r = 0; r < 4; r++)
                        acc[r][j] = ffma2(av[r], b2, acc[r][j]);
                }
            }
        }
        __syncthreads();
    }
}

// ---- per-row layernorm of a 64xD smem tile ----
__device__ __forceinline__ void layernorm_tile(const float* __restrict__ xs,
                                               float* __restrict__ hs,
                                               const float* __restrict__ g,
                                               const float* __restrict__ be, int tid) {
    const int warp = tid >> 5, lane = tid & 31;
#pragma unroll
    for (int rr = 0; rr < 4; rr++) {
        const int r = warp * 4 + rr;
        const float* row = xs + r * D;
        float s = 0.f, s2 = 0.f;
#pragma unroll
        for (int c = lane; c < D; c += 32) { float v = row[c]; s += v; s2 += v * v; }
#pragma unroll
        for (int o = 16; o; o >>= 1) {
            s  += __shfl_xor_sync(0xFFFFFFFFu, s,  o);
            s2 += __shfl_xor_sync(0xFFFFFFFFu, s2, o);
        }
        const float mu   = s * (1.0f / D);
        const float var  = s2 * (1.0f / D) - mu * mu;
        const float rstd = rsqrtf(var + EPS);
#pragma unroll
        for (int c = lane; c < D; c += 32)
            hs[r * D + c] = (row[c] - mu) * rstd * g[c] + be[c];
    }
}

__global__ __launch_bounds__(NTHR, 1)
void stab_embed_fused(const float* __restrict__ meas, const float* __restrict__ event,
                      const float* __restrict__ leak, const float* __restrict__ event_leak,
                      const int* __restrict__ stab_ids, const int* __restrict__ cycle_ids,
                      const float* __restrict__ w_meas, const float* __restrict__ b_meas,
                      const float* __restrict__ w_event, const float* __restrict__ b_event,
                      const float* __restrict__ w_leak, const float* __restrict__ b_leak,
                      const float* __restrict__ w_el, const float* __restrict__ b_el,
                      const float* __restrict__ stab_table, const float* __restrict__ cycle_table,
                      const float* __restrict__ g1, const float* __restrict__ be1,
                      const float* __restrict__ W11, const float* __restrict__ b11,
                      const float* __restrict__ W12, const float* __restrict__ b12,
                      const float* __restrict__ g2, const float* __restrict__ be2,
                      const float* __restrict__ W21, const float* __restrict__ b21,
                      const float* __restrict__ W22, const float* __restrict__ b22,
                      float* __restrict__ out) {
    extern __shared__ float smem[];
    float* xs = smem;              // 64 x 256  residual stream
    float* hs = smem + TM * D;     // 64 x 256  LN / GELU activations
    float* ws = smem + 2 * TM * D; // KC x 256  streamed weight chunk

    const int tid  = threadIdx.x;
    const int base = blockIdx.x * TM;

    // ---- embed: 4 scalar projections + 2 table gathers -> xs ----
    {
        const int r  = tid >> 3;            // 64 rows
        const int c0 = (tid & 7) * 32;      // 32 cols each
        const int gr = base + r;
        const float m  = meas[gr], e = event[gr], l = leak[gr], el = event_leak[gr];
        const float* srow = stab_table  + (size_t)stab_ids[gr]  * D;
        const float* crow = cycle_table + (size_t)cycle_ids[gr] * D;
#pragma unroll
        for (int c = c0; c < c0 + 32; c++) {
            xs[r * D + c] = m * w_meas[c] + b_meas[c]
                          + e * w_event[c] + b_event[c]
                          + l * w_leak[c] + b_leak[c]
                          + el * w_el[c] + b_el[c]
                          + srow[c] + crow[c];
        }
    }
    __syncthreads();

    const int trow = (tid >> 5) * 4;
    const int tcol = (tid & 31) * 2;
    u64 acc[4][4];

    // ================= residual block 1 =================
    layernorm_tile(xs, hs, g1, be1, tid);
    __syncthreads();

    gemm_tile(hs, W11, ws, acc, tid);           // trailing sync inside covers hs reads
#pragma unroll
    for (int r = 0; r < 4; r++)
#pragma unroll
        for (int j = 0; j < 4; j++) {
            const int col = tcol + 64 * j;
            float2 v = unpack2(acc[r][j]);
            hs[(trow + r) * D + col]     = gelu_exact(v.x + b11[col]);
            hs[(trow + r) * D + col + 1] = gelu_exact(v.y + b11[col + 1]);
        }
    __syncthreads();

    gemm_tile(hs, W12, ws, acc, tid);
#pragma unroll
    for (int r = 0; r < 4; r++)
#pragma unroll
        for (int j = 0; j < 4; j++) {
            const int col = tcol + 64 * j;
            float2 v = unpack2(acc[r][j]);
            xs[(trow + r) * D + col]     += v.x + b12[col];
            xs[(trow + r) * D + col + 1] += v.y + b12[col + 1];
        }
    __syncthreads();

    // ================= residual block 2 =================
    layernorm_tile(xs, hs, g2, be2, tid);
    __syncthreads();

    gemm_tile(hs, W21, ws, acc, tid);
#pragma unroll
    for (int r = 0; r < 4; r++)
#pragma unroll
        for (int j = 0; j < 4; j++) {
            const int col = tcol + 64 * j;
            float2 v = unpack2(acc[r][j]);
            hs[(trow + r) * D + col]     = gelu_exact(v.x + b21[col]);
            hs[(trow + r) * D + col + 1] = gelu_exact(v.y + b21[col + 1]);
        }
    __syncthreads();

    gemm_tile(hs, W22, ws, acc, tid);
#pragma unroll
    for (int r = 0; r < 4; r++)
#pragma unroll
        for (int j = 0; j < 4; j++) {
            const int col = tcol + 64 * j;
            float2 v = unpack2(acc[r][j]);
            const size_t o = (size_t)(base + trow + r) * D + col;
            out[o]     = xs[(trow + r) * D + col]     + v.x + b22[col];
            out[o + 1] = xs[(trow + r) * D + col + 1] + v.y + b22[col + 1];
        }
}

extern "C" void kernel_launch(void* const* d_in, const int* in_sizes, int n_in,
                              void* d_out, int out_size) {
    const float* meas       = (const float*)d_in[0];
    const float* event      = (const float*)d_in[1];
    const float* leak       = (const float*)d_in[2];
    const float* event_leak = (const float*)d_in[3];
    const int*   stab_ids   = (const int*)d_in[4];
    const int*   cycle_ids  = (const int*)d_in[5];
    const float* w_meas  = (const float*)d_in[6];
    const float* b_meas  = (const float*)d_in[7];
    const float* w_event = (const float*)d_in[8];
    const float* b_event = (const float*)d_in[9];
    const float* w_leak  = (const float*)d_in[10];
    const float* b_leak  = (const float*)d_in[11];
    const float* w_el    = (const float*)d_in[12];
    const float* b_el    = (const float*)d_in[13];
    const float* stab_table  = (const float*)d_in[14];
    const float* cycle_table = (const float*)d_in[15];
    const float* g1  = (const float*)d_in[16];
    const float* be1 = (const float*)d_in[17];
    const float* W11 = (const float*)d_in[18];
    const float* b11 = (const float*)d_in[19];
    const float* W12 = (const float*)d_in[20];
    const float* b12 = (const float*)d_in[21];
    const float* g2  = (const float*)d_in[22];
    const float* be2 = (const float*)d_in[23];
    const float* W21 = (const float*)d_in[24];
    const float* b21 = (const float*)d_in[25];
    const float* W22 = (const float*)d_in[26];
    const float* b22 = (const float*)d_in[27];

    const int n_tokens = in_sizes[0];          // B*S = 262144
    const int nblocks  = n_tokens / TM;        // 4096
    const int smem_bytes = (2 * TM * D + KC * D) * (int)sizeof(float);  // 147456

    cudaFuncSetAttribute(stab_embed_fused,
                         cudaFuncAttributeMaxDynamicSharedMemorySize, smem_bytes);

    stab_embed_fused<<<nblocks, NTHR, smem_bytes>>>(
        meas, event, leak, event_leak, stab_ids, cycle_ids,
        w_meas, b_meas, w_event, b_event, w_leak, b_leak, w_el, b_el,
        stab_table, cycle_table,
        g1, be1, W11, b11, W12, b12,
        g2, be2, W21, b21, W22, b22,
        (float*)d_out);
}

// round 5
// speedup vs baseline: 2.8227x; 2.8214x over previous
#include <cuda_runtime.h>
#include <cuda_bf16.h>
#include <math.h>
#include <stdint.h>

#define EPS   1e-5f
#define NTHR  256

// ---- SMEM layout (bytes) ----
#define XS_OFF   0
#define AP_OFF   65536                      // 64KB xs pairs [32][256] float2
#define WB0_OFF  135168                     // Apack: 128*68*8 = 69632
#define WB1_OFF  151552
#define PRM_OFF  167936                     // 13 vec * 1KB = 13312
#define PS_OFF   181248
#define PSQ_OFF  181760
#define SMEM_TOTAL 182272

// prepped weights: [gemm][ktile][4096 u32]  (= [nt 32][sel 2][lane 32][which 2])
__device__ __align__(16) uint32_t g_wpack[4][16][4096];

__device__ __forceinline__ uint32_t s2u(const void* p) {
    uint32_t a;
    asm("{ .reg .u64 t; cvta.to.shared.u64 t, %1; cvt.u32.u64 %0, t; }" : "=r"(a) : "l"(p));
    return a;
}

__device__ __forceinline__ void hmma(float* c, const uint32_t* a, uint32_t b0, uint32_t b1) {
    asm volatile("mma.sync.aligned.m16n8k16.row.col.f32.bf16.bf16.f32 "
        "{%0,%1,%2,%3}, {%4,%5,%6,%7}, {%8,%9}, {%0,%1,%2,%3};"
        : "+f"(c[0]), "+f"(c[1]), "+f"(c[2]), "+f"(c[3])
        : "r"(a[0]), "r"(a[1]), "r"(a[2]), "r"(a[3]), "r"(b0), "r"(b1));
}

__device__ __forceinline__ void cp16(uint32_t dst, const void* src) {
    uint64_t gp = __cvta_generic_to_global(src);
    asm volatile("cp.async.cg.shared.global [%0], [%1], 16;" :: "r"(dst), "l"(gp));
}
#define CP_COMMIT() asm volatile("cp.async.commit_group;" ::: "memory")
#define CP_WAIT0()  asm volatile("cp.async.wait_group 0;" ::: "memory")

__device__ __forceinline__ void split2(float v0, float v1, uint32_t& hi, uint32_t& lo) {
    __nv_bfloat162 h = __floats2bfloat162_rn(v0, v1);
    float r0 = v0 - __bfloat162float(h.x);
    float r1 = v1 - __bfloat162float(h.y);
    __nv_bfloat162 l = __floats2bfloat162_rn(r0, r1);
    hi = *reinterpret_cast<uint32_t*>(&h);
    lo = *reinterpret_cast<uint32_t*>(&l);
}

__device__ __forceinline__ float gelu(float x) {
    return 0.5f * x * (1.0f + erff(x * 0.70710678118654752f));
}

// ---- prep: pack W (fp32 [k][n]) into fragment-ready bf16 hi/lo chunks ----
__global__ void prep_w(const float* __restrict__ W11, const float* __restrict__ W12,
                       const float* __restrict__ W21, const float* __restrict__ W22) {
    const float* Ws[4] = {W11, W12, W21, W22};
    int gi = blockIdx.x >> 4, kt = blockIdx.x & 15;
    const float* W = Ws[gi];
    for (int i = threadIdx.x; i < 4096; i += blockDim.x) {
        int which = i & 1, lane = (i >> 1) & 31, sel = (i >> 6) & 1, nt = i >> 7;
        int t = lane & 3, gg = lane >> 2;
        int n = nt * 8 + gg;
        int k = kt * 16 + t * 2 + (which ? 8 : 0);
        float w0 = W[k * 256 + n], w1 = W[(k + 1) * 256 + n];
        __nv_bfloat16 h0 = __float2bfloat16(w0), h1 = __float2bfloat16(w1);
        __nv_bfloat162 r;
        if (sel == 0) { r.x = h0; r.y = h1; }
        else {
            r.x = __float2bfloat16(w0 - __bfloat162float(h0));
            r.y = __float2bfloat16(w1 - __bfloat162float(h1));
        }
        g_wpack[gi][kt][i] = *reinterpret_cast<uint32_t*>(&r);
    }
}

// ---- one fused 64x256x256 GEMM (3-term split), W streamed via cp.async ----
__device__ __forceinline__ void gemm256(char* smem, uint32_t sb, const uint32_t* wsrc,
                                        float (&c)[16][4], int tid, int wn,
                                        int m0g, int m0g8, int t) {
    const uint2* ap = (const uint2*)(smem + AP_OFF);
#pragma unroll
    for (int nt = 0; nt < 16; nt++)
#pragma unroll
        for (int q = 0; q < 4; q++) c[nt][q] = 0.f;

    {   // pre-issue chunk 0
        uint32_t d = sb + WB0_OFF + tid * 16;
        const char* s = (const char*)wsrc + tid * 16;
#pragma unroll
        for (int i = 0; i < 4; i++) cp16(d + i * 4096, s + i * 4096);
        CP_COMMIT();
    }
    for (int kt = 0; kt < 16; kt++) {
        CP_WAIT0();
        __syncthreads();
        if (kt + 1 < 16) {
            uint32_t d = sb + (((kt + 1) & 1) ? WB1_OFF : WB0_OFF) + tid * 16;
            const char* s = (const char*)wsrc + (kt + 1) * 16384 + tid * 16;
#pragma unroll
            for (int i = 0; i < 4; i++) cp16(d + i * 4096, s + i * 4096);
            CP_COMMIT();
        }
        int k2 = kt * 8 + t;
        uint2 p0 = ap[k2 * 68 + m0g];
        uint2 p1 = ap[k2 * 68 + m0g8];
        uint2 p2 = ap[(k2 + 4) * 68 + m0g];
        uint2 p3 = ap[(k2 + 4) * 68 + m0g8];
        uint32_t ahi[4] = {p0.x, p1.x, p2.x, p3.x};
        uint32_t alo[4] = {p0.y, p1.y, p2.y, p3.y};
        const char* wb = smem + ((kt & 1) ? WB1_OFF : WB0_OFF) + (tid & 31) * 8 + wn * 16 * 512;
#pragma unroll
        for (int nt = 0; nt < 16; nt++) {
            uint2 bh = *(const uint2*)(wb + nt * 512);
            uint2 bl = *(const uint2*)(wb + nt * 512 + 256);
            hmma(c[nt], ahi, bh.x, bh.y);
            hmma(c[nt], alo, bh.x, bh.y);
            hmma(c[nt], ahi, bl.x, bl.y);
        }
    }
}

__device__ __forceinline__ void ln_stats(float (&c)[16][4], float* psum, float* psq,
                                         int wn, int m0g, int m0g8, int t,
                                         float& mu0, float& rs0, float& mu1, float& rs1) {
    float s0 = 0, q0 = 0, s1 = 0, q1 = 0;
#pragma unroll
    for (int nt = 0; nt < 16; nt++) {
        s0 += c[nt][0] + c[nt][1]; q0 += c[nt][0] * c[nt][0] + c[nt][1] * c[nt][1];
        s1 += c[nt][2] + c[nt][3]; q1 += c[nt][2] * c[nt][2] + c[nt][3] * c[nt][3];
    }
    s0 += __shfl_xor_sync(~0u, s0, 1); s0 += __shfl_xor_sync(~0u, s0, 2);
    q0 += __shfl_xor_sync(~0u, q0, 1); q0 += __shfl_xor_sync(~0u, q0, 2);
    s1 += __shfl_xor_sync(~0u, s1, 1); s1 += __shfl_xor_sync(~0u, s1, 2);
    q1 += __shfl_xor_sync(~0u, q1, 1); q1 += __shfl_xor_sync(~0u, q1, 2);
    if (t == 0) {
        psum[wn * 64 + m0g] = s0;  psq[wn * 64 + m0g] = q0;
        psum[wn * 64 + m0g8] = s1; psq[wn * 64 + m0g8] = q1;
    }
    __syncthreads();
    float ts0 = psum[m0g] + psum[64 + m0g],  tq0 = psq[m0g] + psq[64 + m0g];
    float ts1 = psum[m0g8] + psum[64 + m0g8], tq1 = psq[m0g8] + psq[64 + m0g8];
    mu0 = ts0 * (1.f / 256.f); rs0 = rsqrtf(tq0 * (1.f / 256.f) - mu0 * mu0 + EPS);
    mu1 = ts1 * (1.f / 256.f); rs1 = rsqrtf(tq1 * (1.f / 256.f) - mu1 * mu1 + EPS);
}

__device__ __forceinline__ void norm_split(float (&c)[16][4], const float* gv, const float* bv,
                                           float mu0, float rs0, float mu1, float rs1,
                                           uint2* ap, int wn, int t, int m0g, int m0g8) {
#pragma unroll
    for (int nt = 0; nt < 16; nt++) {
        int cg = wn * 128 + nt * 8 + t * 2;
        float2 gg = *(const float2*)(gv + cg);
        float2 bb = *(const float2*)(bv + cg);
        float v0 = (c[nt][0] - mu0) * rs0 * gg.x + bb.x;
        float v1 = (c[nt][1] - mu0) * rs0 * gg.y + bb.y;
        float v2 = (c[nt][2] - mu1) * rs1 * gg.x + bb.x;
        float v3 = (c[nt][3] - mu1) * rs1 * gg.y + bb.y;
        uint32_t h01, l01, h23, l23;
        split2(v0, v1, h01, l01);
        split2(v2, v3, h23, l23);
        int k2 = (wn * 16 + nt) * 4 + t;
        ap[k2 * 68 + m0g]  = make_uint2(h01, l01);
        ap[k2 * 68 + m0g8] = make_uint2(h23, l23);
    }
}

__device__ __forceinline__ void gelu_split(float (&c)[16][4], const float* bv,
                                           uint2* ap, int wn, int t, int m0g, int m0g8) {
    __syncthreads();   // all warps out of previous GEMM before Apack overwrite
#pragma unroll
    for (int nt = 0; nt < 16; nt++) {
        int cg = wn * 128 + nt * 8 + t * 2;
        float2 bb = *(const float2*)(bv + cg);
        float v0 = gelu(c[nt][0] + bb.x);
        float v1 = gelu(c[nt][1] + bb.y);
        float v2 = gelu(c[nt][2] + bb.x);
        float v3 = gelu(c[nt][3] + bb.y);
        uint32_t h01, l01, h23, l23;
        split2(v0, v1, h01, l01);
        split2(v2, v3, h23, l23);
        int k2 = (wn * 16 + nt) * 4 + t;
        ap[k2 * 68 + m0g]  = make_uint2(h01, l01);
        ap[k2 * 68 + m0g8] = make_uint2(h23, l23);
    }
}

__global__ void __launch_bounds__(NTHR, 1)
stab_hmma(const float* __restrict__ meas, const float* __restrict__ event,
          const float* __restrict__ leak, const float* __restrict__ event_leak,
          const int* __restrict__ stab_ids, const int* __restrict__ cycle_ids,
          const float* __restrict__ w_meas, const float* __restrict__ b_meas,
          const float* __restrict__ w_event, const float* __restrict__ b_event,
          const float* __restrict__ w_leak, const float* __restrict__ b_leak,
          const float* __restrict__ w_el, const float* __restrict__ b_el,
          const float* __restrict__ stab_table, const float* __restrict__ cycle_table,
          const float* __restrict__ g1, const float* __restrict__ be1,
          const float* __restrict__ b11, const float* __restrict__ b12,
          const float* __restrict__ g2, const float* __restrict__ be2,
          const float* __restrict__ b21, const float* __restrict__ b22,
          float* __restrict__ out) {
    extern __shared__ char smem[];
    const uint32_t sb = s2u(smem);
    float*  prm  = (float*)(smem + PRM_OFF);
    float*  psum = (float*)(smem + PS_OFF);
    float*  psq  = (float*)(smem + PSQ_OFF);
    float2* xsp  = (float2*)(smem + XS_OFF);
    uint2*  ap   = (uint2*)(smem + AP_OFF);

    const int tid = threadIdx.x, w = tid >> 5, lane = tid & 31;
    const int wm = w & 3, wn = w >> 2, t = lane & 3, g = lane >> 2;
    const int m0g = wm * 16 + g, m0g8 = m0g + 8;
    const int base = blockIdx.x * 64;
    const int r0 = base + m0g, r1 = base + m0g8;

    {   // stage params: slot0=bcomb, 1..12 below
        const float* P[12] = {w_meas, w_event, w_leak, w_el, g1, be1, b11, b12, g2, be2, b21, b22};
        for (int i = tid; i < 12 * 256; i += NTHR) prm[256 + i] = P[i >> 8][i & 255];
        for (int i = tid; i < 256; i += NTHR)
            prm[i] = b_meas[i] + b_event[i] + b_leak[i] + b_el[i];
    }
    __syncthreads();

    float c[16][4];

    // ---- embed (values land directly in C/A-fragment layout) ----
    {
        float me0 = meas[r0], me1 = meas[r1];
        float ev0 = event[r0], ev1 = event[r1];
        float lk0 = leak[r0], lk1 = leak[r1];
        float el0 = event_leak[r0], el1 = event_leak[r1];
        const float* st0 = stab_table + (size_t)stab_ids[r0] * 256;
        const float* st1 = stab_table + (size_t)stab_ids[r1] * 256;
        const float* cy0 = cycle_table + (size_t)cycle_ids[r0] * 256;
        const float* cy1 = cycle_table + (size_t)cycle_ids[r1] * 256;
#pragma unroll
        for (int nt = 0; nt < 16; nt++) {
            int cg = wn * 128 + nt * 8 + t * 2;
            float2 bc  = *(const float2*)(prm + 0 * 256 + cg);
            float2 wmv = *(const float2*)(prm + 1 * 256 + cg);
            float2 wev = *(const float2*)(prm + 2 * 256 + cg);
            float2 wlv = *(const float2*)(prm + 3 * 256 + cg);
            float2 wzv = *(const float2*)(prm + 4 * 256 + cg);
            float2 s0 = *(const float2*)(st0 + cg), s1 = *(const float2*)(st1 + cg);
            float2 q0 = *(const float2*)(cy0 + cg), q1 = *(const float2*)(cy1 + cg);
            c[nt][0] = bc.x + me0 * wmv.x + ev0 * wev.x + lk0 * wlv.x + el0 * wzv.x + s0.x + q0.x;
            c[nt][1] = bc.y + me0 * wmv.y + ev0 * wev.y + lk0 * wlv.y + el0 * wzv.y + s0.y + q0.y;
            c[nt][2] = bc.x + me1 * wmv.x + ev1 * wev.x + lk1 * wlv.x + el1 * wzv.x + s1.x + q1.x;
            c[nt][3] = bc.y + me1 * wmv.y + ev1 * wev.y + lk1 * wlv.y + el1 * wzv.y + s1.y + q1.y;
            xsp[(nt * 2 + 0) * 256 + tid] = make_float2(c[nt][0], c[nt][1]);
            xsp[(nt * 2 + 1) * 256 + tid] = make_float2(c[nt][2], c[nt][3]);
        }
    }

    float mu0, rs0, mu1, rs1;
    // LN1 -> Apack
    ln_stats(c, psum, psq, wn, m0g, m0g8, t, mu0, rs0, mu1, rs1);
    norm_split(c, prm + 5 * 256, prm + 6 * 256, mu0, rs0, mu1, rs1, ap, wn, t, m0g, m0g8);

    // GEMM1 = h @ W11 ; GELU(+b11) -> Apack
    gemm256(smem, sb, &g_wpack[0][0][0], c, tid, wn, m0g, m0g8, t);
    gelu_split(c, prm + 7 * 256, ap, wn, t, m0g, m0g8);

    // GEMM2 = h @ W12 ; x += D + b12 ; LN2 -> Apack
    gemm256(smem, sb, &g_wpack[1][0][0], c, tid, wn, m0g, m0g8, t);
#pragma unroll
    for (int nt = 0; nt < 16; nt++) {
        int cg = wn * 128 + nt * 8 + t * 2;
        float2 bb = *(const float2*)(prm + 8 * 256 + cg);
        float2 x0 = xsp[(nt * 2 + 0) * 256 + tid];
        float2 x1 = xsp[(nt * 2 + 1) * 256 + tid];
        c[nt][0] = x0.x + c[nt][0] + bb.x;
        c[nt][1] = x0.y + c[nt][1] + bb.y;
        c[nt][2] = x1.x + c[nt][2] + bb.x;
        c[nt][3] = x1.y + c[nt][3] + bb.y;
        xsp[(nt * 2 + 0) * 256 + tid] = make_float2(c[nt][0], c[nt][1]);
        xsp[(nt * 2 + 1) * 256 + tid] = make_float2(c[nt][2], c[nt][3]);
    }
    ln_stats(c, psum, psq, wn, m0g, m0g8, t, mu0, rs0, mu1, rs1);
    norm_split(c, prm + 9 * 256, prm + 10 * 256, mu0, rs0, mu1, rs1, ap, wn, t, m0g, m0g8);

    // GEMM3 = h @ W21 ; GELU(+b21) -> Apack
    gemm256(smem, sb, &g_wpack[2][0][0], c, tid, wn, m0g, m0g8, t);
    gelu_split(c, prm + 11 * 256, ap, wn, t, m0g, m0g8);

    // GEMM4 = h @ W22 ; out = x + D + b22
    gemm256(smem, sb, &g_wpack[3][0][0], c, tid, wn, m0g, m0g8, t);
#pragma unroll
    for (int nt = 0; nt < 16; nt++) {
        int cg = wn * 128 + nt * 8 + t * 2;
        float2 bb = *(const float2*)(prm + 12 * 256 + cg);
        float2 x0 = xsp[(nt * 2 + 0) * 256 + tid];
        float2 x1 = xsp[(nt * 2 + 1) * 256 + tid];
        *(float2*)(out + (size_t)r0 * 256 + cg) =
            make_float2(x0.x + c[nt][0] + bb.x, x0.y + c[nt][1] + bb.y);
        *(float2*)(out + (size_t)r1 * 256 + cg) =
            make_float2(x1.x + c[nt][2] + bb.x, x1.y + c[nt][3] + bb.y);
    }
}

extern "C" void kernel_launch(void* const* d_in, const int* in_sizes, int n_in,
                              void* d_out, int out_size) {
    const float* meas       = (const float*)d_in[0];
    const float* event      = (const float*)d_in[1];
    const float* leak       = (const float*)d_in[2];
    const float* event_leak = (const float*)d_in[3];
    const int*   stab_ids   = (const int*)d_in[4];
    const int*   cycle_ids  = (const int*)d_in[5];
    const float* w_meas  = (const float*)d_in[6];
    const float* b_meas  = (const float*)d_in[7];
    const float* w_event = (const float*)d_in[8];
    const float* b_event = (const float*)d_in[9];
    const float* w_leak  = (const float*)d_in[10];
    const float* b_leak  = (const float*)d_in[11];
    const float* w_el    = (const float*)d_in[12];
    const float* b_el    = (const float*)d_in[13];
    const float* stab_table  = (const float*)d_in[14];
    const float* cycle_table = (const float*)d_in[15];
    const float* g1  = (const float*)d_in[16];
    const float* be1 = (const float*)d_in[17];
    const float* W11 = (const float*)d_in[18];
    const float* b11 = (const float*)d_in[19];
    const float* W12 = (const float*)d_in[20];
    const float* b12 = (const float*)d_in[21];
    const float* g2  = (const float*)d_in[22];
    const float* be2 = (const float*)d_in[23];
    const float* W21 = (const float*)d_in[24];
    const float* b21 = (const float*)d_in[25];
    const float* W22 = (const float*)d_in[26];
    const float* b22 = (const float*)d_in[27];

    const int n_tokens = in_sizes[0];
    const int nblocks  = n_tokens / 64;    // 4096

    prep_w<<<64, 128>>>(W11, W12, W21, W22);

    cudaFuncSetAttribute(stab_hmma,
                         cudaFuncAttributeMaxDynamicSharedMemorySize, SMEM_TOTAL);
    stab_hmma<<<nblocks, NTHR, SMEM_TOTAL>>>(
        meas, event, leak, event_leak, stab_ids, cycle_ids,
        w_meas, b_meas, w_event, b_event, w_leak, b_leak, w_el, b_el,
        stab_table, cycle_table,
        g1, be1, b11, b12, g2, be2, b21, b22,
        (float*)d_out);
}